// round 2
// baseline (speedup 1.0000x reference)
#include <cuda_runtime.h>

#define BB 8
#define HH 8
#define NN 4096
#define DD 64
#define MM 64

// ---------------- scratch ----------------
__device__ float g_ql[BB*HH*MM*DD];
__device__ float g_kl[BB*HH*MM*DD];
__device__ float g_attn2[BB*HH*MM*MM];
__device__ float g_zinv[BB*HH*MM*MM];
__device__ float g_T2[BB*HH*MM*MM];
__device__ float g_Sp[BB*HH*16*MM*DD];
__device__ float g_M[BB*HH*MM*DD];
__device__ float g_G3a[(size_t)BB*HH*MM*NN];
__device__ float g_G3b[(size_t)BB*HH*MM*NN];
__device__ unsigned int g_maxcol_u, g_maxrow_u;

__global__ void k_init() { g_maxcol_u = 0u; g_maxrow_u = 0u; }

// ---------------- K1: landmarks ----------------
__global__ void k_landmarks(const float* __restrict__ q, const float* __restrict__ k) {
    int bh = blockIdx.x, mi = blockIdx.y, d = threadIdx.x;
    const float* qp = q + ((size_t)bh*NN + (size_t)mi*64)*DD + d;
    const float* kp = k + ((size_t)bh*NN + (size_t)mi*64)*DD + d;
    float sq = 0.f, sk = 0.f;
    #pragma unroll 8
    for (int t = 0; t < 64; t++) { sq += qp[(size_t)t*DD]; sk += kp[(size_t)t*DD]; }
    g_ql[(bh*MM + mi)*DD + d] = sq * (1.f/64.f);
    g_kl[(bh*MM + mi)*DD + d] = sk * (1.f/64.f);
}

// ---------------- K2: sim2 + Wsim2 mix + softmax -> attn2 ----------------
__global__ void k_sim2(const float* __restrict__ Wsim2) {
    extern __shared__ float sm[];
    float* qls = sm;            // 64*65
    float* kls = sm + 4160;     // 64*65
    float* acc = sm + 8320;     // 64*65
    int b = blockIdx.x >> 3, kk = blockIdx.x & 7;
    int t = threadIdx.x;
    for (int x = t; x < 4160; x += 256) acc[x] = 0.f;
    int j = t & 63, ib = t >> 6;
    for (int h = 0; h < 8; h++) {
        __syncthreads();
        const float* qsrc = g_ql + (size_t)(b*8 + h)*4096;
        const float* ksrc = g_kl + (size_t)(b*8 + h)*4096;
        for (int x = t; x < 4096; x += 256) {
            qls[(x>>6)*65 + (x&63)] = qsrc[x];
            kls[(x>>6)*65 + (x&63)] = ksrc[x];
        }
        __syncthreads();
        float w = __ldg(&Wsim2[h*8 + kk]);
        for (int s = 0; s < 16; s++) {
            int i = ib*16 + s;
            float dot = 0.f;
            #pragma unroll
            for (int d = 0; d < 64; d++) dot += qls[i*65 + d] * kls[j*65 + d];
            acc[i*65 + j] += w * dot;
        }
    }
    __syncthreads();
    if (t < 64) {
        float* row = acc + t*65;
        float mx = -3.4e38f;
        for (int jj = 0; jj < 64; jj++) mx = fmaxf(mx, row[jj]);
        float sum = 0.f;
        for (int jj = 0; jj < 64; jj++) { float e = expf(row[jj] - mx); row[jj] = e; sum += e; }
        float inv = 1.f / sum;
        float* dst = g_attn2 + (size_t)blockIdx.x*4096 + t*64;
        for (int jj = 0; jj < 64; jj++) dst[jj] = row[jj] * inv;
    }
}

// ---------------- K3: pinv scaling factors ----------------
__global__ void k_scale() {
    __shared__ float a[64*65];
    int bh = blockIdx.x, t = threadIdx.x;
    for (int x = t; x < 4096; x += 256) a[(x>>6)*65 + (x&63)] = g_attn2[(size_t)bh*4096 + x];
    __syncthreads();
    if (t < 64) {
        float rs = 0.f, cs = 0.f;
        for (int j = 0; j < 64; j++) { rs += a[t*65 + j]; cs += a[j*65 + t]; }
        atomicMax(&g_maxcol_u, __float_as_uint(rs)); // sum over last axis
        atomicMax(&g_maxrow_u, __float_as_uint(cs)); // sum over -2 axis
    }
}

// ---------------- 64x64 smem matmul helper ----------------
__device__ __forceinline__ void mm64(const float* __restrict__ A, const float* __restrict__ B,
                                     float R[16], int ig, int jg) {
    #pragma unroll
    for (int u = 0; u < 16; u++) R[u] = 0.f;
    const float* a0 = A + (ig*4)*65;
    const float* b0 = B + jg*4;
    for (int k = 0; k < 64; k++) {
        float av0 = a0[k], av1 = a0[65 + k], av2 = a0[130 + k], av3 = a0[195 + k];
        float bv0 = b0[k*65], bv1 = b0[k*65+1], bv2 = b0[k*65+2], bv3 = b0[k*65+3];
        R[ 0] += av0*bv0; R[ 1] += av0*bv1; R[ 2] += av0*bv2; R[ 3] += av0*bv3;
        R[ 4] += av1*bv0; R[ 5] += av1*bv1; R[ 6] += av1*bv2; R[ 7] += av1*bv3;
        R[ 8] += av2*bv0; R[ 9] += av2*bv1; R[10] += av2*bv2; R[11] += av2*bv3;
        R[12] += av3*bv0; R[13] += av3*bv1; R[14] += av3*bv2; R[15] += av3*bv3;
    }
}

// ---------------- K4: Moore-Penrose pinv ----------------
__global__ void k_pinv() {
    extern __shared__ float sm[];
    float* xs = sm;
    float* zs = sm + 4160;
    float* ta = sm + 8320;
    float* tb = sm + 12480;
    int bh = blockIdx.x, t = threadIdx.x;
    int ig = t >> 4, jg = t & 15;
    for (int x = t; x < 4096; x += 256) xs[(x>>6)*65 + (x&63)] = g_attn2[(size_t)bh*4096 + x];
    __syncthreads();
    float inv = 1.f / (__uint_as_float(g_maxcol_u) * __uint_as_float(g_maxrow_u));
    for (int x = t; x < 4096; x += 256) {
        int i = x >> 6, j = x & 63;
        zs[i*65 + j] = xs[j*65 + i] * inv;
    }
    __syncthreads();
    float R[16], tv[16];
    for (int it = 0; it < 6; it++) {
        // ta = x @ z
        mm64(xs, zs, R, ig, jg);
        __syncthreads();
        #pragma unroll
        for (int u = 0; u < 16; u++) ta[(ig*4 + (u>>2))*65 + jg*4 + (u&3)] = R[u];
        __syncthreads();
        // tb = 7*ta - ta@ta
        mm64(ta, ta, R, ig, jg);
        #pragma unroll
        for (int u = 0; u < 16; u++) tv[u] = ta[(ig*4 + (u>>2))*65 + jg*4 + (u&3)];
        __syncthreads();
        #pragma unroll
        for (int u = 0; u < 16; u++) tb[(ig*4 + (u>>2))*65 + jg*4 + (u&3)] = 7.f*tv[u] - R[u];
        __syncthreads();
        // tb = 15*ta - ta@tb
        mm64(ta, tb, R, ig, jg);
        __syncthreads();
        #pragma unroll
        for (int u = 0; u < 16; u++) tb[(ig*4 + (u>>2))*65 + jg*4 + (u&3)] = 15.f*tv[u] - R[u];
        __syncthreads();
        // z = 0.25*(13*z - z@tb)
        mm64(zs, tb, R, ig, jg);
        #pragma unroll
        for (int u = 0; u < 16; u++) tv[u] = zs[(ig*4 + (u>>2))*65 + jg*4 + (u&3)];
        __syncthreads();
        #pragma unroll
        for (int u = 0; u < 16; u++) zs[(ig*4 + (u>>2))*65 + jg*4 + (u&3)] = 0.25f*(13.f*tv[u] - R[u]);
        __syncthreads();
    }
    for (int x = t; x < 4096; x += 256) g_zinv[(size_t)bh*4096 + x] = zs[(x>>6)*65 + (x&63)];
}

// ---------------- head mix ----------------
__device__ __forceinline__ void mix_body(const float* __restrict__ in, float* __restrict__ outp,
                                         const float* __restrict__ W, size_t inner, size_t gid) {
    size_t b = gid / inner;
    size_t x = gid - b*inner;
    size_t base = b*8*inner + x;
    float a[8];
    #pragma unroll
    for (int h = 0; h < 8; h++) a[h] = in[base + (size_t)h*inner];
    #pragma unroll
    for (int kk = 0; kk < 8; kk++) {
        float s = 0.f;
        #pragma unroll
        for (int h = 0; h < 8; h++) s += a[h] * __ldg(&W[h*8 + kk]);
        outp[base + (size_t)kk*inner] = s;
    }
}
__global__ void k_mixT2(const float* __restrict__ W) {
    mix_body(g_zinv, g_T2, W, 4096, (size_t)blockIdx.x*256 + threadIdx.x);
}
__global__ void k_mixA3(const float* __restrict__ W) {
    mix_body(g_G3a, g_G3b, W, (size_t)MM*NN, (size_t)blockIdx.x*256 + threadIdx.x);
}

// ---------------- K6: sim3 logits fused with Wsim3 mix ----------------
__global__ void k_sim3(const float* __restrict__ kg, const float* __restrict__ Wsim3) {
    extern __shared__ float sm[];
    float* qls  = sm;                 // 64*65
    float* kt   = sm + 4160;          // 32*65
    float* accm = sm + 6240;          // 8*64*33
    int b = blockIdx.x >> 7, it = blockIdx.x & 127;
    int i0 = it*32;
    int t = threadIdx.x;
    for (int x = t; x < 16896; x += 256) accm[x] = 0.f;
    int ii = t & 31, jb = t >> 5;
    for (int h = 0; h < 8; h++) {
        __syncthreads();
        const float* qsrc = g_ql + (size_t)(b*8 + h)*4096;
        for (int x = t; x < 4096; x += 256) qls[(x>>6)*65 + (x&63)] = qsrc[x];
        const float* ksrc = kg + ((size_t)(b*8 + h)*NN + i0)*DD;
        for (int x = t; x < 2048; x += 256) kt[(x>>6)*65 + (x&63)] = ksrc[x];
        __syncthreads();
        float wv[8];
        #pragma unroll
        for (int kk = 0; kk < 8; kk++) wv[kk] = __ldg(&Wsim3[h*8 + kk]);
        for (int s = 0; s < 8; s++) {
            int j = jb*8 + s;
            float dot = 0.f;
            #pragma unroll
            for (int d = 0; d < 64; d++) dot += qls[j*65 + d] * kt[ii*65 + d];
            #pragma unroll
            for (int kk = 0; kk < 8; kk++) accm[kk*2112 + j*33 + ii] += wv[kk]*dot;
        }
    }
    __syncthreads();
    for (int x = t; x < 16384; x += 256) {
        int i = x & 31, j = (x >> 5) & 63, kk = x >> 11;
        g_G3a[((size_t)(b*8 + kk)*64 + j)*NN + i0 + i] = accm[kk*2112 + j*33 + i];
    }
}

// ---------------- K7: 4096-wide row softmax ----------------
__global__ void k_softmax() {
    __shared__ float red[256];
    size_t base = (size_t)blockIdx.x * NN;
    int t = threadIdx.x;
    float v[16]; float mx = -3.4e38f;
    #pragma unroll
    for (int s = 0; s < 16; s++) { v[s] = g_G3a[base + t + 256*s]; mx = fmaxf(mx, v[s]); }
    red[t] = mx; __syncthreads();
    for (int o = 128; o > 0; o >>= 1) { if (t < o) red[t] = fmaxf(red[t], red[t+o]); __syncthreads(); }
    mx = red[0]; __syncthreads();
    float sum = 0.f;
    #pragma unroll
    for (int s = 0; s < 16; s++) { v[s] = expf(v[s] - mx); sum += v[s]; }
    red[t] = sum; __syncthreads();
    for (int o = 128; o > 0; o >>= 1) { if (t < o) red[t] += red[t+o]; __syncthreads(); }
    float inv = 1.f / red[0];
    #pragma unroll
    for (int s = 0; s < 16; s++) g_G3a[base + t + 256*s] = v[s] * inv;
}

// ---------------- K9: split-K partials of attn3m @ v ----------------
__global__ void k_spart(const float* __restrict__ vg) {
    extern __shared__ float sm[];
    float* At = sm;            // 64*257
    float* vt = sm + 16448;    // 256*65
    int bk = blockIdx.x, p = blockIdx.y;
    int t = threadIdx.x;
    const float* asrc = g_G3b + (size_t)bk*64*NN + p*256;
    for (int x = t; x < 16384; x += 256) { int j = x >> 8, i = x & 255; At[j*257 + i] = asrc[(size_t)j*NN + i]; }
    const float* vsrc = vg + ((size_t)bk*NN + p*256)*DD;
    for (int x = t; x < 16384; x += 256) vt[(x>>6)*65 + (x&63)] = vsrc[x];
    __syncthreads();
    int jg = t >> 4, dg = t & 15;
    float R[16];
    #pragma unroll
    for (int u = 0; u < 16; u++) R[u] = 0.f;
    for (int i = 0; i < 256; i++) {
        float a0 = At[(jg*4+0)*257 + i], a1 = At[(jg*4+1)*257 + i];
        float a2 = At[(jg*4+2)*257 + i], a3 = At[(jg*4+3)*257 + i];
        float b0 = vt[i*65 + dg*4+0], b1 = vt[i*65 + dg*4+1];
        float b2 = vt[i*65 + dg*4+2], b3 = vt[i*65 + dg*4+3];
        R[ 0]+=a0*b0; R[ 1]+=a0*b1; R[ 2]+=a0*b2; R[ 3]+=a0*b3;
        R[ 4]+=a1*b0; R[ 5]+=a1*b1; R[ 6]+=a1*b2; R[ 7]+=a1*b3;
        R[ 8]+=a2*b0; R[ 9]+=a2*b1; R[10]+=a2*b2; R[11]+=a2*b3;
        R[12]+=a3*b0; R[13]+=a3*b1; R[14]+=a3*b2; R[15]+=a3*b3;
    }
    float* dst = g_Sp + ((size_t)bk*16 + p)*4096;
    #pragma unroll
    for (int u = 0; u < 16; u++) dst[(jg*4 + (u>>2))*64 + dg*4 + (u&3)] = R[u];
}

// ---------------- K10: reduce partials; M = T2 @ S ----------------
__global__ void k_mfin() {
    __shared__ float ss[4160];
    __shared__ float t2s[4160];
    int bk = blockIdx.x, t = threadIdx.x;
    for (int x = t; x < 4096; x += 256) {
        float s = 0.f;
        #pragma unroll
        for (int p = 0; p < 16; p++) s += g_Sp[((size_t)bk*16 + p)*4096 + x];
        ss[(x>>6)*65 + (x&63)]  = s;
        t2s[(x>>6)*65 + (x&63)] = g_T2[(size_t)bk*4096 + x];
    }
    __syncthreads();
    float R[16]; int ig = t >> 4, jg = t & 15;
    mm64(t2s, ss, R, ig, jg);
    #pragma unroll
    for (int u = 0; u < 16; u++)
        g_M[(size_t)bk*4096 + (ig*4 + (u>>2))*64 + jg*4 + (u&3)] = R[u];
}

// ---------------- K11: fused sim1 path ----------------
__global__ void k_sim1out(const float* __restrict__ qg,
                          const float* __restrict__ Ws1,
                          const float* __restrict__ Wa1,
                          float* __restrict__ out) {
    extern __shared__ float sm[];
    float* Lm = sm;               // 8 * (32*65) = 16640
    float* kl = sm + 16640;       // 64*65 = 4160 (later reused for M)
    float* qs = sm + 20800;       // 32*65 = 2080
    int b = blockIdx.x >> 7, it = blockIdx.x & 127;
    int i0 = it*32;
    int t = threadIdx.x;
    for (int x = t; x < 16640; x += 256) Lm[x] = 0.f;
    int j = t & 63, ib = t >> 6;
    for (int h = 0; h < 8; h++) {
        __syncthreads();
        const float* ksrc = g_kl + (size_t)(b*8 + h)*4096;
        for (int x = t; x < 4096; x += 256) kl[(x>>6)*65 + (x&63)] = ksrc[x];
        const float* qsrc = qg + ((size_t)(b*8 + h)*NN + i0)*DD;
        for (int x = t; x < 2048; x += 256) qs[(x>>6)*65 + (x&63)] = qsrc[x];
        __syncthreads();
        float wv[8];
        #pragma unroll
        for (int kk = 0; kk < 8; kk++) wv[kk] = __ldg(&Ws1[h*8 + kk]);
        for (int s = 0; s < 8; s++) {
            int i = ib*8 + s;
            float dot = 0.f;
            #pragma unroll
            for (int d = 0; d < 64; d++) dot += qs[i*65 + d] * kl[j*65 + d];
            #pragma unroll
            for (int kk = 0; kk < 8; kk++) Lm[kk*2080 + i*65 + j] += wv[kk]*dot;
        }
    }
    __syncthreads();
    // softmax over j (64) for each (kk,i)
    {
        int kk = t >> 5, i = t & 31;
        float* row = Lm + kk*2080 + i*65;
        float mx = -3.4e38f;
        for (int jj = 0; jj < 64; jj++) mx = fmaxf(mx, row[jj]);
        float sum = 0.f;
        for (int jj = 0; jj < 64; jj++) { float e = expf(row[jj] - mx); row[jj] = e; sum += e; }
        float inv = 1.f / sum;
        for (int jj = 0; jj < 64; jj++) row[jj] *= inv;
    }
    __syncthreads();
    // in-place mix with Wattn1 over the kk axis
    for (int s = 0; s < 8; s++) {
        int x = t + 256*s;           // 2048 (i,j) pairs
        int i = x >> 6, jj = x & 63;
        float a[8], m[8];
        #pragma unroll
        for (int kk = 0; kk < 8; kk++) a[kk] = Lm[kk*2080 + i*65 + jj];
        #pragma unroll
        for (int k2 = 0; k2 < 8; k2++) {
            float sv = 0.f;
            #pragma unroll
            for (int kk = 0; kk < 8; kk++) sv += a[kk] * __ldg(&Wa1[kk*8 + k2]);
            m[k2] = sv;
        }
        #pragma unroll
        for (int k2 = 0; k2 < 8; k2++) Lm[k2*2080 + i*65 + jj] = m[k2];
    }
    __syncthreads();
    // out[b,k2,i0+i,d] = sum_j Lm[k2,i,j] * M[b,k2,j,d]
    for (int k2 = 0; k2 < 8; k2++) {
        const float* msrc = g_M + (size_t)(b*8 + k2)*4096;
        for (int x = t; x < 4096; x += 256) kl[(x>>6)*65 + (x&63)] = msrc[x];
        __syncthreads();
        for (int s = 0; s < 8; s++) {
            int x = t + 256*s;       // 2048 (i,d) pairs
            int i = x >> 6, d = x & 63;
            const float* arow = Lm + k2*2080 + i*65;
            float acc = 0.f;
            #pragma unroll
            for (int jj = 0; jj < 64; jj++) acc += arow[jj] * kl[jj*65 + d];
            out[((size_t)(b*8 + k2)*NN + i0 + i)*DD + d] = acc;
        }
        __syncthreads();
    }
}

// ---------------- K12: residual conv, out += res ----------------
__global__ void __launch_bounds__(512) k_conv(const float* __restrict__ vg,
                                              const float* __restrict__ cw,
                                              float* __restrict__ out) {
    extern __shared__ float sm[];
    float* vv = sm;            // 8h * 48n * 64d = 24576
    float* ws = sm + 24576;    // 8*8*33 = 2112
    int b = blockIdx.x >> 8, nt = blockIdx.x & 255;
    int n0 = nt*16;
    int t = threadIdx.x;
    for (int h = 0; h < 8; h++) {
        for (int x = t; x < 3072; x += 512) {
            int i = x >> 6, d = x & 63;
            int na = n0 - 16 + i;
            float val = 0.f;
            if (na >= 0 && na < NN) val = vg[((size_t)(b*8 + h)*NN + na)*DD + d];
            vv[h*3072 + i*64 + d] = val;
        }
    }
    for (int x = t; x < 2112; x += 512) ws[x] = cw[x];
    __syncthreads();
    int k = t >> 6, d = t & 63;
    float acc[16];
    #pragma unroll
    for (int n = 0; n < 16; n++) acc[n] = 0.f;
    float vreg[48];
    for (int h = 0; h < 8; h++) {
        #pragma unroll
        for (int i = 0; i < 48; i++) vreg[i] = vv[h*3072 + i*64 + d];
        const float* wrow = ws + k*264 + h*33;
        #pragma unroll
        for (int tt = 0; tt < 33; tt++) {
            float wv = wrow[tt];
            #pragma unroll
            for (int n = 0; n < 16; n++) acc[n] += wv * vreg[n + tt];
        }
    }
    size_t obase = ((size_t)(b*8 + k)*NN + n0)*DD + d;
    #pragma unroll
    for (int n = 0; n < 16; n++) out[obase + (size_t)n*DD] += acc[n];
}

// ---------------- launch ----------------
extern "C" void kernel_launch(void* const* d_in, const int* in_sizes, int n_in,
                              void* d_out, int out_size) {
    const float* q   = (const float*)d_in[0];
    const float* k   = (const float*)d_in[1];
    const float* v   = (const float*)d_in[2];
    const float* Ws1 = (const float*)d_in[3];
    const float* Ws2 = (const float*)d_in[4];
    const float* Ws3 = (const float*)d_in[5];
    const float* Wa1 = (const float*)d_in[6];
    const float* Wa2 = (const float*)d_in[7];
    const float* Wa3 = (const float*)d_in[8];
    const float* cw  = (const float*)d_in[9];
    float* out = (float*)d_out;

    cudaFuncSetAttribute(k_sim2,    cudaFuncAttributeMaxDynamicSharedMemorySize, 49920);
    cudaFuncSetAttribute(k_pinv,    cudaFuncAttributeMaxDynamicSharedMemorySize, 66560);
    cudaFuncSetAttribute(k_sim3,    cudaFuncAttributeMaxDynamicSharedMemorySize, 92544);
    cudaFuncSetAttribute(k_spart,   cudaFuncAttributeMaxDynamicSharedMemorySize, 132352);
    cudaFuncSetAttribute(k_sim1out, cudaFuncAttributeMaxDynamicSharedMemorySize, 91520);
    cudaFuncSetAttribute(k_conv,    cudaFuncAttributeMaxDynamicSharedMemorySize, 106752);

    k_init<<<1, 1>>>();
    k_landmarks<<<dim3(64, 64), 64>>>(q, k);
    k_sim2<<<64, 256, 49920>>>(Ws2);
    k_scale<<<64, 256>>>();
    k_pinv<<<64, 256, 66560>>>();
    k_mixT2<<<128, 256>>>(Wa2);
    k_sim3<<<1024, 256, 92544>>>(k, Ws3);
    k_softmax<<<4096, 256>>>();
    k_mixA3<<<8192, 256>>>(Wa3);
    k_spart<<<dim3(64, 16), 256, 132352>>>(v);
    k_mfin<<<64, 256>>>();
    k_sim1out<<<1024, 256, 91520>>>(q, Ws1, Wa1, out);
    k_conv<<<2048, 512, 106752>>>(v, cw, out);
}

// round 3
// speedup vs baseline: 1.2914x; 1.2914x over previous
#include <cuda_runtime.h>

#define BB 8
#define HH 8
#define NN 4096
#define DD 64
#define MM 64

// ---------------- scratch ----------------
__device__ float g_ql[BB*HH*MM*DD];
__device__ float g_kl[BB*HH*MM*DD];
__device__ float g_attn2[BB*HH*MM*MM];
__device__ float g_zinv[BB*HH*MM*MM];
__device__ float g_T2[BB*HH*MM*MM];
__device__ float g_Sp[BB*HH*16*MM*DD];
__device__ float g_M[BB*HH*MM*DD];
__device__ float g_G3a[(size_t)BB*HH*MM*NN];
__device__ float g_G3b[(size_t)BB*HH*MM*NN];
__device__ unsigned int g_maxcol_u, g_maxrow_u;

__global__ void k_init() { g_maxcol_u = 0u; g_maxrow_u = 0u; }

__device__ __forceinline__ void ffma2(float2& a, const float2 b, const float2 c) {
    asm("fma.rn.f32x2 %0, %1, %2, %0;"
        : "+l"(reinterpret_cast<unsigned long long&>(a))
        : "l"(reinterpret_cast<const unsigned long long&>(b)),
          "l"(reinterpret_cast<const unsigned long long&>(c)));
}

// ---------------- K1: landmarks ----------------
__global__ void k_landmarks(const float* __restrict__ q, const float* __restrict__ k) {
    int bh = blockIdx.x, mi = blockIdx.y, d = threadIdx.x;
    const float* qp = q + ((size_t)bh*NN + (size_t)mi*64)*DD + d;
    const float* kp = k + ((size_t)bh*NN + (size_t)mi*64)*DD + d;
    float sq = 0.f, sk = 0.f;
    #pragma unroll 8
    for (int t = 0; t < 64; t++) { sq += qp[(size_t)t*DD]; sk += kp[(size_t)t*DD]; }
    g_ql[(bh*MM + mi)*DD + d] = sq * (1.f/64.f);
    g_kl[(bh*MM + mi)*DD + d] = sk * (1.f/64.f);
}

// 4x4 register-tile dot: rows from A (stride 65), cols from B (stride 65),
// interleaved mapping: row r -> ig+16r, col c -> jg+16c  (conflict-free)
__device__ __forceinline__ void dot4x4(const float* __restrict__ A, const float* __restrict__ B,
                                       float R[16], int ig, int jg) {
    #pragma unroll
    for (int u = 0; u < 16; u++) R[u] = 0.f;
    #pragma unroll 8
    for (int d = 0; d < 64; d++) {
        float a0 = A[(ig    )*65 + d], a1 = A[(ig+16)*65 + d];
        float a2 = A[(ig+32)*65 + d], a3 = A[(ig+48)*65 + d];
        float b0 = B[(jg    )*65 + d], b1 = B[(jg+16)*65 + d];
        float b2 = B[(jg+32)*65 + d], b3 = B[(jg+48)*65 + d];
        R[ 0]+=a0*b0; R[ 1]+=a0*b1; R[ 2]+=a0*b2; R[ 3]+=a0*b3;
        R[ 4]+=a1*b0; R[ 5]+=a1*b1; R[ 6]+=a1*b2; R[ 7]+=a1*b3;
        R[ 8]+=a2*b0; R[ 9]+=a2*b1; R[10]+=a2*b2; R[11]+=a2*b3;
        R[12]+=a3*b0; R[13]+=a3*b1; R[14]+=a3*b2; R[15]+=a3*b3;
    }
}

#define RAWS 4164   // per-head raw stride (64*65 + 4 pad -> distinct banks per h)

// in-place 8h -> 8k mix at smem position p across 8 raw planes
__device__ __forceinline__ void mix8(float* __restrict__ raw, const float* __restrict__ ws, int p) {
    float a[8];
    #pragma unroll
    for (int h = 0; h < 8; h++) a[h] = raw[h*RAWS + p];
    #pragma unroll
    for (int kk = 0; kk < 8; kk++) {
        float s = 0.f;
        #pragma unroll
        for (int h = 0; h < 8; h++) s += a[h] * ws[h*8 + kk];
        raw[kk*RAWS + p] = s;
    }
}

// ---------------- K2: sim2 dots(once) + mix + softmax + scale sums ----------------
__global__ void __launch_bounds__(256) k_sim2scale(const float* __restrict__ Wsim2) {
    extern __shared__ float sm[];
    float* qa  = sm;             // 64*65
    float* ka  = sm + 4160;      // 64*65
    float* raw = sm + 8320;      // 8*RAWS
    float* ws  = sm + 8320 + 8*RAWS; // 64
    int b = blockIdx.x;
    int t = threadIdx.x;
    if (t < 64) ws[t] = Wsim2[t];
    int ig = t >> 4, jg = t & 15;
    for (int h = 0; h < 8; h++) {
        __syncthreads();
        const float* qsrc = g_ql + (size_t)(b*8 + h)*4096;
        const float* ksrc = g_kl + (size_t)(b*8 + h)*4096;
        for (int x = t; x < 4096; x += 256) {
            qa[(x>>6)*65 + (x&63)] = qsrc[x];
            ka[(x>>6)*65 + (x&63)] = ksrc[x];
        }
        __syncthreads();
        float R[16];
        dot4x4(qa, ka, R, ig, jg);
        float* rh = raw + h*RAWS;
        #pragma unroll
        for (int u = 0; u < 16; u++) rh[(ig + 16*(u>>2))*65 + jg + 16*(u&3)] = R[u];
    }
    __syncthreads();
    for (int x = t; x < 4096; x += 256) mix8(raw, ws, (x>>6)*65 + (x&63));
    __syncthreads();
    // softmax each (kk,i) row; atomicMax of post-softmax row sums (axis=-1 sums)
    #pragma unroll
    for (int s = 0; s < 2; s++) {
        int rr = t + 256*s;
        float* row = raw + (rr>>6)*RAWS + (rr&63)*65;
        float mx = -3.4e38f;
        for (int j = 0; j < 64; j++) mx = fmaxf(mx, row[j]);
        float sum = 0.f;
        for (int j = 0; j < 64; j++) { float e = __expf(row[j] - mx); row[j] = e; sum += e; }
        float inv = 1.f / sum;
        float rs = 0.f;
        for (int j = 0; j < 64; j++) { float vv = row[j]*inv; row[j] = vv; rs += vv; }
        atomicMax(&g_maxcol_u, __float_as_uint(rs));
    }
    __syncthreads();
    // column sums (axis=-2)
    #pragma unroll
    for (int s = 0; s < 2; s++) {
        int cc = t + 256*s;
        const float* base = raw + (cc>>6)*RAWS + (cc&63);
        float cs = 0.f;
        for (int i = 0; i < 64; i++) cs += base[i*65];
        atomicMax(&g_maxrow_u, __float_as_uint(cs));
    }
    // write attn2
    for (int x = t; x < 32768; x += 256) {
        int kk = x >> 12, i = (x >> 6) & 63, j = x & 63;
        g_attn2[(size_t)(b*8 + kk)*4096 + i*64 + j] = raw[kk*RAWS + i*65 + j];
    }
}

// ---------------- 64x64 smem matmul helper ----------------
__device__ __forceinline__ void mm64(const float* __restrict__ A, const float* __restrict__ B,
                                     float R[16], int ig, int jg) {
    #pragma unroll
    for (int u = 0; u < 16; u++) R[u] = 0.f;
    const float* a0 = A + (ig*4)*65;
    const float* b0 = B + jg*4;
    for (int k = 0; k < 64; k++) {
        float av0 = a0[k], av1 = a0[65 + k], av2 = a0[130 + k], av3 = a0[195 + k];
        float bv0 = b0[k*65], bv1 = b0[k*65+1], bv2 = b0[k*65+2], bv3 = b0[k*65+3];
        R[ 0] += av0*bv0; R[ 1] += av0*bv1; R[ 2] += av0*bv2; R[ 3] += av0*bv3;
        R[ 4] += av1*bv0; R[ 5] += av1*bv1; R[ 6] += av1*bv2; R[ 7] += av1*bv3;
        R[ 8] += av2*bv0; R[ 9] += av2*bv1; R[10] += av2*bv2; R[11] += av2*bv3;
        R[12] += av3*bv0; R[13] += av3*bv1; R[14] += av3*bv2; R[15] += av3*bv3;
    }
}

// ---------------- K4: Moore-Penrose pinv ----------------
__global__ void k_pinv() {
    extern __shared__ float sm[];
    float* xs = sm;
    float* zs = sm + 4160;
    float* ta = sm + 8320;
    float* tb = sm + 12480;
    int bh = blockIdx.x, t = threadIdx.x;
    int ig = t >> 4, jg = t & 15;
    for (int x = t; x < 4096; x += 256) xs[(x>>6)*65 + (x&63)] = g_attn2[(size_t)bh*4096 + x];
    __syncthreads();
    float inv = 1.f / (__uint_as_float(g_maxcol_u) * __uint_as_float(g_maxrow_u));
    for (int x = t; x < 4096; x += 256) {
        int i = x >> 6, j = x & 63;
        zs[i*65 + j] = xs[j*65 + i] * inv;
    }
    __syncthreads();
    float R[16], tv[16];
    for (int it = 0; it < 6; it++) {
        mm64(xs, zs, R, ig, jg);
        __syncthreads();
        #pragma unroll
        for (int u = 0; u < 16; u++) ta[(ig*4 + (u>>2))*65 + jg*4 + (u&3)] = R[u];
        __syncthreads();
        mm64(ta, ta, R, ig, jg);
        #pragma unroll
        for (int u = 0; u < 16; u++) tv[u] = ta[(ig*4 + (u>>2))*65 + jg*4 + (u&3)];
        __syncthreads();
        #pragma unroll
        for (int u = 0; u < 16; u++) tb[(ig*4 + (u>>2))*65 + jg*4 + (u&3)] = 7.f*tv[u] - R[u];
        __syncthreads();
        mm64(ta, tb, R, ig, jg);
        __syncthreads();
        #pragma unroll
        for (int u = 0; u < 16; u++) tb[(ig*4 + (u>>2))*65 + jg*4 + (u&3)] = 15.f*tv[u] - R[u];
        __syncthreads();
        mm64(zs, tb, R, ig, jg);
        #pragma unroll
        for (int u = 0; u < 16; u++) tv[u] = zs[(ig*4 + (u>>2))*65 + jg*4 + (u&3)];
        __syncthreads();
        #pragma unroll
        for (int u = 0; u < 16; u++) zs[(ig*4 + (u>>2))*65 + jg*4 + (u&3)] = 0.25f*(13.f*tv[u] - R[u]);
        __syncthreads();
    }
    for (int x = t; x < 4096; x += 256) g_zinv[(size_t)bh*4096 + x] = zs[(x>>6)*65 + (x&63)];
}

// ---------------- head mix (streaming) ----------------
__device__ __forceinline__ void mix_body(const float* __restrict__ in, float* __restrict__ outp,
                                         const float* __restrict__ W, size_t inner, size_t gid) {
    size_t b = gid / inner;
    size_t x = gid - b*inner;
    size_t base = b*8*inner + x;
    float a[8];
    #pragma unroll
    for (int h = 0; h < 8; h++) a[h] = in[base + (size_t)h*inner];
    #pragma unroll
    for (int kk = 0; kk < 8; kk++) {
        float s = 0.f;
        #pragma unroll
        for (int h = 0; h < 8; h++) s += a[h] * __ldg(&W[h*8 + kk]);
        outp[base + (size_t)kk*inner] = s;
    }
}
__global__ void k_mixT2(const float* __restrict__ W) {
    mix_body(g_zinv, g_T2, W, 4096, (size_t)blockIdx.x*256 + threadIdx.x);
}
__global__ void k_mixA3(const float* __restrict__ W) {
    mix_body(g_G3a, g_G3b, W, (size_t)MM*NN, (size_t)blockIdx.x*256 + threadIdx.x);
}

// ---------------- K6: sim3 logits (raw dots -> mix) ----------------
__global__ void __launch_bounds__(256) k_sim3(const float* __restrict__ kg, const float* __restrict__ Wsim3) {
    extern __shared__ float sm[];
    float* qls = sm;             // 64*65
    float* kt  = sm + 4160;      // 64*65
    float* raw = sm + 8320;      // 8*RAWS
    float* ws  = sm + 8320 + 8*RAWS;
    int b = blockIdx.x >> 6, it = blockIdx.x & 63;
    int i0 = it*64;
    int t = threadIdx.x;
    if (t < 64) ws[t] = Wsim3[t];
    int ig = t >> 4, jg = t & 15;
    for (int h = 0; h < 8; h++) {
        __syncthreads();
        const float* qsrc = g_ql + (size_t)(b*8 + h)*4096;
        for (int x = t; x < 4096; x += 256) qls[(x>>6)*65 + (x&63)] = qsrc[x];
        const float* ksrc = kg + ((size_t)(b*8 + h)*NN + i0)*DD;
        for (int x = t; x < 4096; x += 256) kt[(x>>6)*65 + (x&63)] = ksrc[x];
        __syncthreads();
        float R[16];
        dot4x4(qls, kt, R, ig, jg);   // rows j (landmark), cols i (token)
        float* rh = raw + h*RAWS;
        #pragma unroll
        for (int u = 0; u < 16; u++) rh[(ig + 16*(u>>2))*65 + jg + 16*(u&3)] = R[u];
    }
    __syncthreads();
    for (int x = t; x < 4096; x += 256) mix8(raw, ws, (x>>6)*65 + (x&63));
    __syncthreads();
    for (int x = t; x < 32768; x += 256) {
        int i = x & 63, j = (x >> 6) & 63, kk = x >> 12;
        g_G3a[((size_t)(b*8 + kk)*64 + j)*NN + i0 + i] = raw[kk*RAWS + j*65 + i];
    }
}

// ---------------- K7: 4096-wide row softmax ----------------
__global__ void k_softmax() {
    __shared__ float red[256];
    size_t base = (size_t)blockIdx.x * NN;
    int t = threadIdx.x;
    float v[16]; float mx = -3.4e38f;
    #pragma unroll
    for (int s = 0; s < 16; s++) { v[s] = g_G3a[base + t + 256*s]; mx = fmaxf(mx, v[s]); }
    red[t] = mx; __syncthreads();
    for (int o = 128; o > 0; o >>= 1) { if (t < o) red[t] = fmaxf(red[t], red[t+o]); __syncthreads(); }
    mx = red[0]; __syncthreads();
    float sum = 0.f;
    #pragma unroll
    for (int s = 0; s < 16; s++) { v[s] = __expf(v[s] - mx); sum += v[s]; }
    red[t] = sum; __syncthreads();
    for (int o = 128; o > 0; o >>= 1) { if (t < o) red[t] += red[t+o]; __syncthreads(); }
    float inv = 1.f / red[0];
    #pragma unroll
    for (int s = 0; s < 16; s++) g_G3a[base + t + 256*s] = v[s] * inv;
}

// ---------------- K9: split-K partials of attn3m @ v ----------------
__global__ void k_spart(const float* __restrict__ vg) {
    extern __shared__ float sm[];
    float* At = sm;            // 64*257
    float* vt = sm + 16448;    // 256*65
    int bk = blockIdx.x, p = blockIdx.y;
    int t = threadIdx.x;
    const float* asrc = g_G3b + (size_t)bk*64*NN + p*256;
    for (int x = t; x < 16384; x += 256) { int j = x >> 8, i = x & 255; At[j*257 + i] = asrc[(size_t)j*NN + i]; }
    const float* vsrc = vg + ((size_t)bk*NN + p*256)*DD;
    for (int x = t; x < 16384; x += 256) vt[(x>>6)*65 + (x&63)] = vsrc[x];
    __syncthreads();
    int jg = t >> 4, dg = t & 15;
    float R[16];
    #pragma unroll
    for (int u = 0; u < 16; u++) R[u] = 0.f;
    for (int i = 0; i < 256; i++) {
        float a0 = At[(jg*4+0)*257 + i], a1 = At[(jg*4+1)*257 + i];
        float a2 = At[(jg*4+2)*257 + i], a3 = At[(jg*4+3)*257 + i];
        float b0 = vt[i*65 + dg*4+0], b1 = vt[i*65 + dg*4+1];
        float b2 = vt[i*65 + dg*4+2], b3 = vt[i*65 + dg*4+3];
        R[ 0]+=a0*b0; R[ 1]+=a0*b1; R[ 2]+=a0*b2; R[ 3]+=a0*b3;
        R[ 4]+=a1*b0; R[ 5]+=a1*b1; R[ 6]+=a1*b2; R[ 7]+=a1*b3;
        R[ 8]+=a2*b0; R[ 9]+=a2*b1; R[10]+=a2*b2; R[11]+=a2*b3;
        R[12]+=a3*b0; R[13]+=a3*b1; R[14]+=a3*b2; R[15]+=a3*b3;
    }
    float* dst = g_Sp + ((size_t)bk*16 + p)*4096;
    #pragma unroll
    for (int u = 0; u < 16; u++) dst[(jg*4 + (u>>2))*64 + dg*4 + (u&3)] = R[u];
}

// ---------------- K10: reduce partials; M = T2 @ S ----------------
__global__ void k_mfin() {
    __shared__ float ss[4160];
    __shared__ float t2s[4160];
    int bk = blockIdx.x, t = threadIdx.x;
    for (int x = t; x < 4096; x += 256) {
        float s = 0.f;
        #pragma unroll
        for (int p = 0; p < 16; p++) s += g_Sp[((size_t)bk*16 + p)*4096 + x];
        ss[(x>>6)*65 + (x&63)]  = s;
        t2s[(x>>6)*65 + (x&63)] = g_T2[(size_t)bk*4096 + x];
    }
    __syncthreads();
    float R[16]; int ig = t >> 4, jg = t & 15;
    mm64(t2s, ss, R, ig, jg);
    #pragma unroll
    for (int u = 0; u < 16; u++)
        g_M[(size_t)bk*4096 + (ig*4 + (u>>2))*64 + jg*4 + (u&3)] = R[u];
}

// ---------------- K11: fused sim1 path ----------------
__global__ void __launch_bounds__(256) k_sim1out(const float* __restrict__ qg,
                          const float* __restrict__ Ws1,
                          const float* __restrict__ Wa1,
                          float* __restrict__ out) {
    extern __shared__ float sm[];
    float* st1 = sm;             // 64*65 : kl, later M
    float* st2 = sm + 4160;      // 64*65 : q rows
    float* raw = sm + 8320;      // 8*RAWS
    float* wsa = sm + 8320 + 8*RAWS;      // 64 (Ws1)
    float* wsb = wsa + 64;                // 64 (Wa1)
    int b = blockIdx.x >> 6, it = blockIdx.x & 63;
    int i0 = it*64;
    int t = threadIdx.x;
    if (t < 64) { wsa[t] = Ws1[t]; wsb[t] = Wa1[t]; }
    int ig = t >> 4, jg = t & 15;
    // A: raw dots per head: raw[h][i][j], i = query token (local), j = landmark
    for (int h = 0; h < 8; h++) {
        __syncthreads();
        const float* ksrc = g_kl + (size_t)(b*8 + h)*4096;
        for (int x = t; x < 4096; x += 256) st1[(x>>6)*65 + (x&63)] = ksrc[x];
        const float* qsrc = qg + ((size_t)(b*8 + h)*NN + i0)*DD;
        for (int x = t; x < 4096; x += 256) st2[(x>>6)*65 + (x&63)] = qsrc[x];
        __syncthreads();
        float R[16];
        dot4x4(st2, st1, R, ig, jg);   // rows i (q), cols j (kl)
        float* rh = raw + h*RAWS;
        #pragma unroll
        for (int u = 0; u < 16; u++) rh[(ig + 16*(u>>2))*65 + jg + 16*(u&3)] = R[u];
    }
    __syncthreads();
    // B: mix Wsim1
    for (int x = t; x < 4096; x += 256) mix8(raw, wsa, (x>>6)*65 + (x&63));
    __syncthreads();
    // C: softmax over j for each (kk,i)
    #pragma unroll
    for (int s = 0; s < 2; s++) {
        int rr = t + 256*s;
        float* row = raw + (rr>>6)*RAWS + (rr&63)*65;
        float mx = -3.4e38f;
        for (int j = 0; j < 64; j++) mx = fmaxf(mx, row[j]);
        float sum = 0.f;
        for (int j = 0; j < 64; j++) { float e = __expf(row[j] - mx); row[j] = e; sum += e; }
        float inv = 1.f / sum;
        for (int j = 0; j < 64; j++) row[j] *= inv;
    }
    __syncthreads();
    // D: mix Wattn1
    for (int x = t; x < 4096; x += 256) mix8(raw, wsb, (x>>6)*65 + (x&63));
    __syncthreads();
    // E: out[kk, i, d] = sum_j raw[kk][i][j] * M[kk][j][d]
    for (int kk = 0; kk < 8; kk++) {
        const float* msrc = g_M + (size_t)(b*8 + kk)*4096;
        for (int x = t; x < 4096; x += 256) st1[(x>>6)*65 + (x&63)] = msrc[x];
        __syncthreads();
        const float* rk = raw + kk*RAWS;
        float R[16];
        #pragma unroll
        for (int u = 0; u < 16; u++) R[u] = 0.f;
        #pragma unroll 8
        for (int j = 0; j < 64; j++) {
            float a0 = rk[(ig    )*65 + j], a1 = rk[(ig+16)*65 + j];
            float a2 = rk[(ig+32)*65 + j], a3 = rk[(ig+48)*65 + j];
            float b0 = st1[j*65 + jg    ], b1 = st1[j*65 + jg+16];
            float b2 = st1[j*65 + jg+32], b3 = st1[j*65 + jg+48];
            R[ 0]+=a0*b0; R[ 1]+=a0*b1; R[ 2]+=a0*b2; R[ 3]+=a0*b3;
            R[ 4]+=a1*b0; R[ 5]+=a1*b1; R[ 6]+=a1*b2; R[ 7]+=a1*b3;
            R[ 8]+=a2*b0; R[ 9]+=a2*b1; R[10]+=a2*b2; R[11]+=a2*b3;
            R[12]+=a3*b0; R[13]+=a3*b1; R[14]+=a3*b2; R[15]+=a3*b3;
        }
        size_t ob = ((size_t)(b*8 + kk)*NN + i0)*DD;
        #pragma unroll
        for (int u = 0; u < 16; u++)
            out[ob + (size_t)(ig + 16*(u>>2))*DD + jg + 16*(u&3)] = R[u];
        __syncthreads();
    }
}

// ---------------- K12: residual conv (f32x2), out += res ----------------
__global__ void __launch_bounds__(256) k_conv(const float* __restrict__ vg,
                                              const float* __restrict__ cw,
                                              float* __restrict__ out) {
    extern __shared__ float sm[];
    float2* vv2 = (float2*)sm;      // 8h * 48n * 32dp float2 = 98304 B
    float* ws = sm + 24576;         // 2112 floats
    int b = blockIdx.x >> 8, nt = blockIdx.x & 255;
    int n0 = nt*16;
    int t = threadIdx.x;
    const float2* vg2 = (const float2*)vg;
    for (int x = t; x < 12288; x += 256) {
        int h = x / 1536, rem = x - h*1536;
        int i = rem >> 5, dp = rem & 31;
        int na = n0 - 16 + i;
        float2 val = make_float2(0.f, 0.f);
        if (na >= 0 && na < NN) val = vg2[((size_t)(b*8 + h)*NN + na)*32 + dp];
        vv2[h*1536 + i*32 + dp] = val;
    }
    for (int x = t; x < 2112; x += 256) ws[x] = cw[x];
    __syncthreads();
    int k = t >> 5, dp = t & 31;
    float2 acc[16];
    #pragma unroll
    for (int n = 0; n < 16; n++) acc[n] = make_float2(0.f, 0.f);
    float2 vr[48];
    for (int h = 0; h < 8; h++) {
        #pragma unroll
        for (int i = 0; i < 48; i++) vr[i] = vv2[h*1536 + i*32 + dp];
        const float* wrow = ws + k*264 + h*33;
        #pragma unroll
        for (int tt = 0; tt < 33; tt++) {
            float w = wrow[tt];
            float2 w2 = make_float2(w, w);
            #pragma unroll
            for (int n = 0; n < 16; n++) ffma2(acc[n], w2, vr[n + tt]);
        }
    }
    float2* op = (float2*)out + ((size_t)(b*8 + k)*NN + n0)*32 + dp;
    #pragma unroll
    for (int n = 0; n < 16; n++) {
        float2 cur = op[(size_t)n*32];
        cur.x += acc[n].x; cur.y += acc[n].y;
        op[(size_t)n*32] = cur;
    }
}

// ---------------- launch ----------------
extern "C" void kernel_launch(void* const* d_in, const int* in_sizes, int n_in,
                              void* d_out, int out_size) {
    const float* q   = (const float*)d_in[0];
    const float* k   = (const float*)d_in[1];
    const float* v   = (const float*)d_in[2];
    const float* Ws1 = (const float*)d_in[3];
    const float* Ws2 = (const float*)d_in[4];
    const float* Ws3 = (const float*)d_in[5];
    const float* Wa1 = (const float*)d_in[6];
    const float* Wa2 = (const float*)d_in[7];
    const float* Wa3 = (const float*)d_in[8];
    const float* cw  = (const float*)d_in[9];
    float* out = (float*)d_out;

    const int SMEM_BIG  = (8320 + 8*RAWS + 128) * 4;  // 167040
    cudaFuncSetAttribute(k_sim2scale, cudaFuncAttributeMaxDynamicSharedMemorySize, SMEM_BIG);
    cudaFuncSetAttribute(k_pinv,      cudaFuncAttributeMaxDynamicSharedMemorySize, 66560);
    cudaFuncSetAttribute(k_sim3,      cudaFuncAttributeMaxDynamicSharedMemorySize, SMEM_BIG);
    cudaFuncSetAttribute(k_spart,     cudaFuncAttributeMaxDynamicSharedMemorySize, 132352);
    cudaFuncSetAttribute(k_sim1out,   cudaFuncAttributeMaxDynamicSharedMemorySize, SMEM_BIG);
    cudaFuncSetAttribute(k_conv,      cudaFuncAttributeMaxDynamicSharedMemorySize, 106752);

    k_init<<<1, 1>>>();
    k_landmarks<<<dim3(64, 64), 64>>>(q, k);
    k_sim2scale<<<8, 256, SMEM_BIG>>>(Ws2);
    k_pinv<<<64, 256, 66560>>>();
    k_mixT2<<<128, 256>>>(Wa2);
    k_sim3<<<512, 256, SMEM_BIG>>>(k, Ws3);
    k_softmax<<<4096, 256>>>();
    k_mixA3<<<8192, 256>>>(Wa3);
    k_spart<<<dim3(64, 16), 256, 132352>>>(v);
    k_mfin<<<64, 256>>>();
    k_sim1out<<<512, 256, SMEM_BIG>>>(q, Ws1, Wa1, out);
    k_conv<<<2048, 256, 106752>>>(v, cw, out);
}

// round 4
// speedup vs baseline: 1.4737x; 1.1412x over previous
#include <cuda_runtime.h>

#define BB 8
#define HH 8
#define NN 4096
#define DD 64
#define MM 64
#define TS 66          // tile row stride (even -> float2 aligned, conflict-free B reads)
#define PS 4232        // raw plane stride (64*66 + 8)

// ---------------- scratch ----------------
__device__ float g_ql[BB*HH*MM*DD];
__device__ float g_kl[BB*HH*MM*DD];
__device__ float g_attn2[BB*HH*MM*MM];
__device__ float g_zinv[BB*HH*MM*MM];
__device__ float g_T2[BB*HH*MM*MM];
__device__ float g_Sp[BB*HH*16*MM*DD];
__device__ float g_M[BB*HH*MM*DD];
__device__ float g_G3a[(size_t)BB*HH*MM*NN];   // mixed sim3 logits (also sim2 scratch)
__device__ float g_G3b[(size_t)BB*HH*MM*NN];   // normalized+mixed attn3
__device__ float g_stats[BB*HH*MM*2];          // per-row max, 1/sum
__device__ unsigned int g_maxcol_u, g_maxrow_u;

__global__ void k_init() { g_maxcol_u = 0u; g_maxrow_u = 0u; }

__device__ __forceinline__ void ffma2(float2& a, float b, const float2 c) {
    float2 bb = make_float2(b, b);
    asm("fma.rn.f32x2 %0, %1, %2, %0;"
        : "+l"(reinterpret_cast<unsigned long long&>(a))
        : "l"(reinterpret_cast<const unsigned long long&>(bb)),
          "l"(reinterpret_cast<const unsigned long long&>(c)));
}

// standard GEMM microtile: C[i][j] = sum_k A[i][k]*B[k][j]
// A row-major stride AS (column reads, warp-broadcast), B row-major stride TS.
// thread (ig,jg): rows ig+16r, col pairs (2jg,2jg+1) and (2jg+32,2jg+33)
template<int L, int AS>
__device__ __forceinline__ void mmstd(const float* __restrict__ A, const float* __restrict__ B,
                                      float2 R[8], int ig, int jg) {
    #pragma unroll
    for (int u = 0; u < 8; u++) R[u] = make_float2(0.f, 0.f);
    #pragma unroll 4
    for (int k = 0; k < L; k++) {
        float a0 = A[(ig     )*AS + k];
        float a1 = A[(ig + 16)*AS + k];
        float a2 = A[(ig + 32)*AS + k];
        float a3 = A[(ig + 48)*AS + k];
        float2 b0 = *(const float2*)&B[k*TS + 2*jg];
        float2 b1 = *(const float2*)&B[k*TS + 2*jg + 32];
        ffma2(R[0], a0, b0); ffma2(R[1], a0, b1);
        ffma2(R[2], a1, b0); ffma2(R[3], a1, b1);
        ffma2(R[4], a2, b0); ffma2(R[5], a2, b1);
        ffma2(R[6], a3, b0); ffma2(R[7], a3, b1);
    }
}

template<int S>
__device__ __forceinline__ void storeR(float* __restrict__ dst, const float2 R[8], int ig, int jg) {
    #pragma unroll
    for (int r = 0; r < 4; r++) {
        *(float2*)&dst[(size_t)(ig + 16*r)*S + 2*jg]      = R[r*2];
        *(float2*)&dst[(size_t)(ig + 16*r)*S + 2*jg + 32] = R[r*2 + 1];
    }
}

// in-place 8h -> 8k mix at smem position p across 8 planes (stride PS)
__device__ __forceinline__ void mix8(float* __restrict__ raw, const float* __restrict__ ws, int p) {
    float a[8];
    #pragma unroll
    for (int h = 0; h < 8; h++) a[h] = raw[h*PS + p];
    #pragma unroll
    for (int kk = 0; kk < 8; kk++) {
        float s = 0.f;
        #pragma unroll
        for (int h = 0; h < 8; h++) s += a[h] * ws[h*8 + kk];
        raw[kk*PS + p] = s;
    }
}

// ---------------- K1: landmarks ----------------
__global__ void k_landmarks(const float* __restrict__ q, const float* __restrict__ k) {
    int bh = blockIdx.x, mi = blockIdx.y, d = threadIdx.x;
    const float* qp = q + ((size_t)bh*NN + (size_t)mi*64)*DD + d;
    const float* kp = k + ((size_t)bh*NN + (size_t)mi*64)*DD + d;
    float sq = 0.f, sk = 0.f;
    #pragma unroll 8
    for (int t = 0; t < 64; t++) { sq += qp[(size_t)t*DD]; sk += kp[(size_t)t*DD]; }
    g_ql[(bh*MM + mi)*DD + d] = sq * (1.f/64.f);
    g_kl[(bh*MM + mi)*DD + d] = sk * (1.f/64.f);
}

// ---------------- K2a: sim2 raw dots per (b,h) -> g_G3a scratch ----------------
__global__ void __launch_bounds__(256) k_sim2dots() {
    __shared__ float qa[64*TS];
    __shared__ float kb[64*TS];
    int bh = blockIdx.x, t = threadIdx.x;
    const float* qsrc = g_ql + (size_t)bh*4096;
    const float* ksrc = g_kl + (size_t)bh*4096;
    for (int x = t; x < 4096; x += 256) {
        int i = x >> 6, d = x & 63;
        qa[i*TS + d] = qsrc[x];
        kb[d*TS + i] = ksrc[x];  // transpose -> B layout [d][j]
    }
    __syncthreads();
    int ig = t >> 4, jg = t & 15;
    float2 R[8];
    mmstd<64, TS>(qa, kb, R, ig, jg);
    storeR<64>(g_G3a + (size_t)bh*4096, R, ig, jg);
}

// ---------------- K2b: mix + softmax + scale sums -> attn2 ----------------
__global__ void __launch_bounds__(256) k_sim2mix(const float* __restrict__ W) {
    __shared__ float acc[64*TS];
    int b = blockIdx.x >> 3, kk = blockIdx.x & 7;
    int t = threadIdx.x;
    float w[8];
    #pragma unroll
    for (int h = 0; h < 8; h++) w[h] = __ldg(&W[h*8 + kk]);
    for (int x = t; x < 4096; x += 256) {
        float s = 0.f;
        #pragma unroll
        for (int h = 0; h < 8; h++) s += g_G3a[(size_t)(b*8 + h)*4096 + x] * w[h];
        acc[(x>>6)*TS + (x&63)] = s;
    }
    __syncthreads();
    if (t < 64) {
        float* row = acc + t*TS;
        float mx = -3.4e38f;
        for (int j = 0; j < 64; j++) mx = fmaxf(mx, row[j]);
        float sum = 0.f;
        for (int j = 0; j < 64; j++) { float e = __expf(row[j] - mx); row[j] = e; sum += e; }
        float inv = 1.f / sum;
        float rs = 0.f;
        for (int j = 0; j < 64; j++) { float vv = row[j]*inv; row[j] = vv; rs += vv; }
        atomicMax(&g_maxcol_u, __float_as_uint(rs));  // row sums (axis=-1)
    }
    __syncthreads();
    if (t < 64) {
        float cs = 0.f;
        for (int i = 0; i < 64; i++) cs += acc[i*TS + t];
        atomicMax(&g_maxrow_u, __float_as_uint(cs));  // col sums (axis=-2)
    }
    for (int x = t; x < 4096; x += 256)
        g_attn2[(size_t)blockIdx.x*4096 + x] = acc[(x>>6)*TS + (x&63)];
}

// ---------------- K4: Moore-Penrose pinv (f32x2) ----------------
__global__ void __launch_bounds__(256) k_pinv() {
    extern __shared__ float sm[];
    float* xs = sm;              // 64*TS each
    float* zs = sm + 4224;
    float* ta = sm + 8448;
    float* tb = sm + 12672;
    int bh = blockIdx.x, t = threadIdx.x;
    int ig = t >> 4, jg = t & 15;
    for (int x = t; x < 4096; x += 256) xs[(x>>6)*TS + (x&63)] = g_attn2[(size_t)bh*4096 + x];
    __syncthreads();
    float inv = 1.f / (__uint_as_float(g_maxcol_u) * __uint_as_float(g_maxrow_u));
    for (int x = t; x < 4096; x += 256) {
        int i = x >> 6, j = x & 63;
        zs[i*TS + j] = xs[j*TS + i] * inv;
    }
    __syncthreads();
    float2 R[8], tv[8];
    for (int it = 0; it < 6; it++) {
        mmstd<64, TS>(xs, zs, R, ig, jg);        // ta = x@z
        __syncthreads();
        storeR<TS>(ta, R, ig, jg);
        __syncthreads();
        mmstd<64, TS>(ta, ta, R, ig, jg);        // ta@ta
        #pragma unroll
        for (int r = 0; r < 4; r++) {
            tv[r*2]   = *(float2*)&ta[(ig+16*r)*TS + 2*jg];
            tv[r*2+1] = *(float2*)&ta[(ig+16*r)*TS + 2*jg + 32];
        }
        __syncthreads();
        #pragma unroll
        for (int r = 0; r < 4; r++) {            // tb = 7*ta - ta@ta
            float2 v0 = make_float2(7.f*tv[r*2].x - R[r*2].x, 7.f*tv[r*2].y - R[r*2].y);
            float2 v1 = make_float2(7.f*tv[r*2+1].x - R[r*2+1].x, 7.f*tv[r*2+1].y - R[r*2+1].y);
            *(float2*)&tb[(ig+16*r)*TS + 2*jg] = v0;
            *(float2*)&tb[(ig+16*r)*TS + 2*jg + 32] = v1;
        }
        __syncthreads();
        mmstd<64, TS>(ta, tb, R, ig, jg);        // ta@tb
        __syncthreads();
        #pragma unroll
        for (int r = 0; r < 4; r++) {            // tb = 15*ta - ta@tb
            float2 v0 = make_float2(15.f*tv[r*2].x - R[r*2].x, 15.f*tv[r*2].y - R[r*2].y);
            float2 v1 = make_float2(15.f*tv[r*2+1].x - R[r*2+1].x, 15.f*tv[r*2+1].y - R[r*2+1].y);
            *(float2*)&tb[(ig+16*r)*TS + 2*jg] = v0;
            *(float2*)&tb[(ig+16*r)*TS + 2*jg + 32] = v1;
        }
        __syncthreads();
        mmstd<64, TS>(zs, tb, R, ig, jg);        // z@tb
        #pragma unroll
        for (int r = 0; r < 4; r++) {
            tv[r*2]   = *(float2*)&zs[(ig+16*r)*TS + 2*jg];
            tv[r*2+1] = *(float2*)&zs[(ig+16*r)*TS + 2*jg + 32];
        }
        __syncthreads();
        #pragma unroll
        for (int r = 0; r < 4; r++) {            // z = 0.25*(13z - z@tb)
            float2 v0 = make_float2(0.25f*(13.f*tv[r*2].x - R[r*2].x), 0.25f*(13.f*tv[r*2].y - R[r*2].y));
            float2 v1 = make_float2(0.25f*(13.f*tv[r*2+1].x - R[r*2+1].x), 0.25f*(13.f*tv[r*2+1].y - R[r*2+1].y));
            *(float2*)&zs[(ig+16*r)*TS + 2*jg] = v0;
            *(float2*)&zs[(ig+16*r)*TS + 2*jg + 32] = v1;
        }
        __syncthreads();
    }
    for (int x = t; x < 4096; x += 256) g_zinv[(size_t)bh*4096 + x] = zs[(x>>6)*TS + (x&63)];
}

// ---------------- K5: T2 = mix(zinv, Wattn2) ----------------
__global__ void k_mixT2(const float* __restrict__ W) {
    size_t gid = (size_t)blockIdx.x*256 + threadIdx.x;
    size_t b = gid / 4096, x = gid - b*4096;
    size_t base = b*8*4096 + x;
    float a[8];
    #pragma unroll
    for (int h = 0; h < 8; h++) a[h] = g_zinv[base + (size_t)h*4096];
    #pragma unroll
    for (int kk = 0; kk < 8; kk++) {
        float s = 0.f;
        #pragma unroll
        for (int h = 0; h < 8; h++) s += a[h] * __ldg(&W[h*8 + kk]);
        g_T2[base + (size_t)kk*4096] = s;
    }
}

// ---------------- K6: sim3 logits + Wsim3 mix -> g_G3a ----------------
__global__ void __launch_bounds__(256) k_sim3(const float* __restrict__ kg, const float* __restrict__ Ws3) {
    extern __shared__ float sm[];
    float* qls = sm;             // 4224
    float* ktb = sm + 4224;      // 4224
    float* raw = sm + 8448;      // 8*PS
    float* ws  = sm + 8448 + 8*PS;
    int b = blockIdx.x >> 6, it = blockIdx.x & 63;
    int i0 = it*64;
    int t = threadIdx.x;
    if (t < 64) ws[t] = Ws3[t];
    int ig = t >> 4, jg = t & 15;
    for (int h = 0; h < 8; h++) {
        __syncthreads();
        const float* qsrc = g_ql + (size_t)(b*8 + h)*4096;
        for (int x = t; x < 4096; x += 256) qls[(x>>6)*TS + (x&63)] = qsrc[x];
        const float* ksrc = kg + ((size_t)(b*8 + h)*NN + i0)*DD;
        for (int x = t; x < 4096; x += 256) ktb[(x&63)*TS + (x>>6)] = ksrc[x];  // transpose [d][i]
        __syncthreads();
        float2 R[8];
        mmstd<64, TS>(qls, ktb, R, ig, jg);   // C[j][i]
        storeR<TS>(raw + h*PS, R, ig, jg);
    }
    __syncthreads();
    for (int x = t; x < 4096; x += 256) mix8(raw, ws, (x>>6)*TS + (x&63));
    __syncthreads();
    for (int x = t; x < 16384; x += 256) {   // float2 copies
        int ip = x & 31, j = (x >> 5) & 63, kk = x >> 11;
        *(float2*)&g_G3a[((size_t)(b*8 + kk)*64 + j)*NN + i0 + 2*ip] =
            *(float2*)&raw[kk*PS + j*TS + 2*ip];
    }
}

// ---------------- K7: per-row max & 1/sum of exp ----------------
__global__ void k_rowstat() {
    __shared__ float red[256];
    size_t base = (size_t)blockIdx.x * NN;
    int t = threadIdx.x;
    float v[16], mx = -3.4e38f;
    #pragma unroll
    for (int s = 0; s < 16; s++) { v[s] = g_G3a[base + t + 256*s]; mx = fmaxf(mx, v[s]); }
    red[t] = mx; __syncthreads();
    for (int o = 128; o > 0; o >>= 1) { if (t < o) red[t] = fmaxf(red[t], red[t+o]); __syncthreads(); }
    mx = red[0]; __syncthreads();
    float sum = 0.f;
    #pragma unroll
    for (int s = 0; s < 16; s++) sum += __expf(v[s] - mx);
    red[t] = sum; __syncthreads();
    for (int o = 128; o > 0; o >>= 1) { if (t < o) red[t] += red[t+o]; __syncthreads(); }
    if (t == 0) { g_stats[blockIdx.x*2] = mx; g_stats[blockIdx.x*2 + 1] = 1.f/red[0]; }
}

// ---------------- K8: fused exp-normalize + Wattn3 mix -> g_G3b ----------------
__global__ void __launch_bounds__(256) k_a3norm(const float* __restrict__ Wa3) {
    int b = blockIdx.y;
    int x = blockIdx.x*256 + threadIdx.x;   // float2 index within batch: 0..131071
    int j = x >> 11, i2 = x & 2047;
    float2 e[8];
    #pragma unroll
    for (int kk = 0; kk < 8; kk++) {
        size_t row = (size_t)(b*8 + kk)*64 + j;
        float2 v = *(const float2*)&g_G3a[row*NN + 2*i2];
        float mx = g_stats[row*2], inv = g_stats[row*2 + 1];
        e[kk] = make_float2(__expf(v.x - mx)*inv, __expf(v.y - mx)*inv);
    }
    #pragma unroll
    for (int k2 = 0; k2 < 8; k2++) {
        float2 s = make_float2(0.f, 0.f);
        #pragma unroll
        for (int kk = 0; kk < 8; kk++) ffma2(s, __ldg(&Wa3[kk*8 + k2]), e[kk]);
        *(float2*)&g_G3b[((size_t)(b*8 + k2)*64 + j)*NN + 2*i2] = s;
    }
}

// ---------------- K9: split-K partials of attn3m @ v ----------------
__global__ void __launch_bounds__(256) k_spart(const float* __restrict__ vg) {
    extern __shared__ float sm[];
    float* At = sm;            // 64*258 = 16512
    float* vt = sm + 16512;    // 256*TS = 16896
    int bk = blockIdx.x, p = blockIdx.y;
    int t = threadIdx.x;
    const float* asrc = g_G3b + (size_t)bk*64*NN + p*256;
    for (int x = t; x < 16384; x += 256) { int j = x >> 8, i = x & 255; At[j*258 + i] = asrc[(size_t)j*NN + i]; }
    const float* vsrc = vg + ((size_t)bk*NN + p*256)*DD;
    for (int x = t; x < 16384; x += 256) vt[(x>>6)*TS + (x&63)] = vsrc[x];
    __syncthreads();
    int ig = t >> 4, jg = t & 15;
    float2 R[8];
    mmstd<256, 258>(At, vt, R, ig, jg);
    storeR<64>(g_Sp + ((size_t)bk*16 + p)*4096, R, ig, jg);
}

// ---------------- K10: reduce partials; M = T2 @ S ----------------
__global__ void __launch_bounds__(256) k_mfin() {
    __shared__ float ss[64*TS];
    __shared__ float t2s[64*TS];
    int bk = blockIdx.x, t = threadIdx.x;
    for (int x = t; x < 4096; x += 256) {
        float s = 0.f;
        #pragma unroll
        for (int p = 0; p < 16; p++) s += g_Sp[((size_t)bk*16 + p)*4096 + x];
        ss[(x>>6)*TS + (x&63)]  = s;
        t2s[(x>>6)*TS + (x&63)] = g_T2[(size_t)bk*4096 + x];
    }
    __syncthreads();
    int ig = t >> 4, jg = t & 15;
    float2 R[8];
    mmstd<64, TS>(t2s, ss, R, ig, jg);
    storeR<64>(g_M + (size_t)bk*4096, R, ig, jg);
}

// ---------------- K11: fused sim1 path ----------------
__global__ void __launch_bounds__(256) k_sim1out(const float* __restrict__ qg,
                          const float* __restrict__ Ws1,
                          const float* __restrict__ Wa1,
                          float* __restrict__ out) {
    extern __shared__ float sm[];
    float* st1 = sm;             // 4224: klT / M
    float* st2 = sm + 4224;      // 4224: q rows
    float* raw = sm + 8448;      // 8*PS
    float* wsa = sm + 8448 + 8*PS;
    float* wsb = wsa + 64;
    int b = blockIdx.x >> 6, it = blockIdx.x & 63;
    int i0 = it*64;
    int t = threadIdx.x;
    if (t < 64) { wsa[t] = Ws1[t]; wsb[t] = Wa1[t]; }
    int ig = t >> 4, jg = t & 15;
    // A: per-head raw dots C[i][j] = q[i]·kl[j]
    for (int h = 0; h < 8; h++) {
        __syncthreads();
        const float* ksrc = g_kl + (size_t)(b*8 + h)*4096;
        for (int x = t; x < 4096; x += 256) st1[(x&63)*TS + (x>>6)] = ksrc[x];  // [d][j]
        const float* qsrc = qg + ((size_t)(b*8 + h)*NN + i0)*DD;
        for (int x = t; x < 4096; x += 256) st2[(x>>6)*TS + (x&63)] = qsrc[x];
        __syncthreads();
        float2 R[8];
        mmstd<64, TS>(st2, st1, R, ig, jg);
        storeR<TS>(raw + h*PS, R, ig, jg);
    }
    __syncthreads();
    for (int x = t; x < 4096; x += 256) mix8(raw, wsa, (x>>6)*TS + (x&63));
    __syncthreads();
    #pragma unroll
    for (int s = 0; s < 2; s++) {        // softmax over j, 512 rows
        int rr = t + 256*s;
        float* row = raw + (rr>>6)*PS + (rr&63)*TS;
        float mx = -3.4e38f;
        for (int j = 0; j < 64; j++) mx = fmaxf(mx, row[j]);
        float sum = 0.f;
        for (int j = 0; j < 64; j++) { float e = __expf(row[j] - mx); row[j] = e; sum += e; }
        float inv = 1.f / sum;
        for (int j = 0; j < 64; j++) row[j] *= inv;
    }
    __syncthreads();
    for (int x = t; x < 4096; x += 256) mix8(raw, wsb, (x>>6)*TS + (x&63));
    __syncthreads();
    // E: out = attn1m @ M
    for (int kk = 0; kk < 8; kk++) {
        const float* msrc = g_M + (size_t)(b*8 + kk)*4096;
        for (int x = t; x < 4096; x += 256) st1[(x>>6)*TS + (x&63)] = msrc[x];
        __syncthreads();
        float2 R[8];
        mmstd<64, TS>(raw + kk*PS, st1, R, ig, jg);
        size_t ob = ((size_t)(b*8 + kk)*NN + i0)*DD;
        #pragma unroll
        for (int r = 0; r < 4; r++) {
            *(float2*)&out[ob + (size_t)(ig + 16*r)*DD + 2*jg]      = R[r*2];
            *(float2*)&out[ob + (size_t)(ig + 16*r)*DD + 2*jg + 32] = R[r*2 + 1];
        }
        __syncthreads();
    }
}

// ---------------- K12: residual conv (f32x2), out += res ----------------
__device__ __forceinline__ void ffma2v(float2& a, const float2 b, const float2 c) {
    asm("fma.rn.f32x2 %0, %1, %2, %0;"
        : "+l"(reinterpret_cast<unsigned long long&>(a))
        : "l"(reinterpret_cast<const unsigned long long&>(b)),
          "l"(reinterpret_cast<const unsigned long long&>(c)));
}
__global__ void __launch_bounds__(256) k_conv(const float* __restrict__ vg,
                                              const float* __restrict__ cw,
                                              float* __restrict__ out) {
    extern __shared__ float sm[];
    float2* vv2 = (float2*)sm;      // 8h * 48n * 32dp float2
    float* ws = sm + 24576;         // 2112 floats
    int b = blockIdx.x >> 8, nt = blockIdx.x & 255;
    int n0 = nt*16;
    int t = threadIdx.x;
    const float2* vg2 = (const float2*)vg;
    for (int x = t; x < 12288; x += 256) {
        int h = x / 1536, rem = x - h*1536;
        int i = rem >> 5, dp = rem & 31;
        int na = n0 - 16 + i;
        float2 val = make_float2(0.f, 0.f);
        if (na >= 0 && na < NN) val = vg2[((size_t)(b*8 + h)*NN + na)*32 + dp];
        vv2[h*1536 + i*32 + dp] = val;
    }
    for (int x = t; x < 2112; x += 256) ws[x] = cw[x];
    __syncthreads();
    int k = t >> 5, dp = t & 31;
    float2 acc[16];
    #pragma unroll
    for (int n = 0; n < 16; n++) acc[n] = make_float2(0.f, 0.f);
    float2 vr[48];
    for (int h = 0; h < 8; h++) {
        #pragma unroll
        for (int i = 0; i < 48; i++) vr[i] = vv2[h*1536 + i*32 + dp];
        const float* wrow = ws + k*264 + h*33;
        #pragma unroll
        for (int tt = 0; tt < 33; tt++) {
            float2 w2 = make_float2(wrow[tt], wrow[tt]);
            #pragma unroll
            for (int n = 0; n < 16; n++) ffma2v(acc[n], w2, vr[n + tt]);
        }
    }
    float2* op = (float2*)out + ((size_t)(b*8 + k)*NN + n0)*32 + dp;
    #pragma unroll
    for (int n = 0; n < 16; n++) {
        float2 cur = op[(size_t)n*32];
        cur.x += acc[n].x; cur.y += acc[n].y;
        op[(size_t)n*32] = cur;
    }
}

// ---------------- launch ----------------
extern "C" void kernel_launch(void* const* d_in, const int* in_sizes, int n_in,
                              void* d_out, int out_size) {
    const float* q   = (const float*)d_in[0];
    const float* k   = (const float*)d_in[1];
    const float* v   = (const float*)d_in[2];
    const float* Ws1 = (const float*)d_in[3];
    const float* Ws2 = (const float*)d_in[4];
    const float* Ws3 = (const float*)d_in[5];
    const float* Wa1 = (const float*)d_in[6];
    const float* Wa2 = (const float*)d_in[7];
    const float* Wa3 = (const float*)d_in[8];
    const float* cw  = (const float*)d_in[9];
    float* out = (float*)d_out;

    const int SMEM_PINV = 16896*4;                      // 67584
    const int SMEM_SIM  = (8448 + 8*PS + 128)*4;        // 169984
    const int SMEM_SPART = (16512 + 256*TS)*4;          // 133632
    cudaFuncSetAttribute(k_pinv,    cudaFuncAttributeMaxDynamicSharedMemorySize, SMEM_PINV);
    cudaFuncSetAttribute(k_sim3,    cudaFuncAttributeMaxDynamicSharedMemorySize, SMEM_SIM);
    cudaFuncSetAttribute(k_spart,   cudaFuncAttributeMaxDynamicSharedMemorySize, SMEM_SPART);
    cudaFuncSetAttribute(k_sim1out, cudaFuncAttributeMaxDynamicSharedMemorySize, SMEM_SIM);
    cudaFuncSetAttribute(k_conv,    cudaFuncAttributeMaxDynamicSharedMemorySize, 106752);

    k_init<<<1, 1>>>();
    k_landmarks<<<dim3(64, 64), 64>>>(q, k);
    k_sim2dots<<<64, 256>>>();
    k_sim2mix<<<64, 256>>>(Ws2);
    k_pinv<<<64, 256, SMEM_PINV>>>();
    k_mixT2<<<128, 256>>>(Wa2);
    k_sim3<<<512, 256, SMEM_SIM>>>(k, Ws3);
    k_rowstat<<<4096, 256>>>();
    k_a3norm<<<dim3(512, 8), 256>>>(Wa3);
    k_spart<<<dim3(64, 16), 256, SMEM_SPART>>>(v);
    k_mfin<<<64, 256>>>();
    k_sim1out<<<512, 256, SMEM_SIM>>>(q, Ws1, Wa1, out);
    k_conv<<<2048, 256, 106752>>>(v, cw, out);
}